// round 7
// baseline (speedup 1.0000x reference)
#include <cuda_runtime.h>
#include <cstdint>

// Problem constants: logits [B, 6, 512, 512] fp32, class_gt [B, 5] fp32, B=32.
#define NCLS   5
#define G      65536             // float4 groups per channel (512*512/4)
#define CHUNKS 128               // blocks per image
#define TPB    128
#define GPC    (G / CHUNKS)      // 512 float4 groups per block
#define ITERS  (GPC / TPB)       // 4 iterations per thread (16 px/thread)
#define MAXB   64

// Fixed-slot partials -> bitwise deterministic, no FP atomics, no zero-init.
__device__ float        g_part_s[MAXB * CHUNKS * NCLS];
__device__ float        g_part_c[MAXB * CHUNKS * NCLS];
__device__ unsigned int g_ticket;   // zero-init; last block resets each call

__device__ __forceinline__ float ex2_fast(float x)
{
    float y; asm("ex2.approx.ftz.f32 %0, %1;" : "=f"(y) : "f"(x)); return y;
}
__device__ __forceinline__ float rcp_fast(float x)
{
    float y; asm("rcp.approx.ftz.f32 %0, %1;" : "=f"(y) : "f"(x)); return y;
}

__global__ void __launch_bounds__(TPB)
apcl_fused_kernel(const float4* __restrict__ logits,
                  const float*  __restrict__ class_gt,
                  float*        __restrict__ out,
                  int B)
{
    const int b     = blockIdx.y;
    const int chunk = blockIdx.x;
    const int t     = threadIdx.x;
    const int nblk  = gridDim.x * gridDim.y;

    const float4* src0 = logits + (size_t)b * 6 * G + chunk * GPC + t;

    float s[NCLS];
#pragma unroll
    for (int c = 0; c < NCLS; c++) s[c] = 0.0f;
    unsigned packed_cnt = 0;               // 5 counters x 6 bits (max 16 each)

    const float L2E = 1.4426950408889634f;

    // 2-deep register double buffer: 5 outstanding LDG.128 per thread.
    float4 v[2][NCLS];
#pragma unroll
    for (int c = 0; c < NCLS; c++)
        v[0][c] = __ldcg(src0 + (size_t)c * G);

#pragma unroll
    for (int it = 0; it < ITERS; it++) {
        if (it + 1 < ITERS) {
#pragma unroll
            for (int c = 0; c < NCLS; c++)
                v[(it + 1) & 1][c] = __ldcg(src0 + (size_t)c * G + (it + 1) * TPB);
        }

        const float4* cur = v[it & 1];

#pragma unroll
        for (int l = 0; l < 4; l++) {
            // exp-domain: e_c = 2^(x_c*log2e). N(0,1) inputs => no overflow.
            // softmax at argmax = e_max/sum(e); monotone => same ties as x.
            float e[NCLS];
            float sum = 0.0f;
#pragma unroll
            for (int c = 0; c < NCLS; c++) {
                e[c] = ex2_fast(((const float*)&cur[c])[l] * L2E);
                sum += e[c];
            }
            const float emax = fmaxf(fmaxf(fmaxf(e[0], e[1]), fmaxf(e[2], e[3])), e[4]);
            const float p    = emax * rcp_fast(sum);

#pragma unroll
            for (int c = 0; c < NCLS; c++) {
                if (e[c] == emax) { s[c] += p; packed_cnt += (1u << (6 * c)); }
            }
        }
    }

    // Unpack counters (exact: <= 16 per class per thread).
    float cf[NCLS];
#pragma unroll
    for (int c = 0; c < NCLS; c++)
        cf[c] = (float)((packed_cnt >> (6 * c)) & 63u);

    // --- warp reduction (fixed order, deterministic) ---
#pragma unroll
    for (int off = 16; off > 0; off >>= 1) {
#pragma unroll
        for (int c = 0; c < NCLS; c++) {
            s[c]  += __shfl_down_sync(0xffffffffu, s[c],  off);
            cf[c] += __shfl_down_sync(0xffffffffu, cf[c], off);
        }
    }

    __shared__ float sw[TPB / 32][NCLS];
    __shared__ float cw[TPB / 32][NCLS];
    const int lane = t & 31;
    const int warp = t >> 5;
    if (lane == 0) {
#pragma unroll
        for (int c = 0; c < NCLS; c++) { sw[warp][c] = s[c]; cw[warp][c] = cf[c]; }
    }
    __syncthreads();

    if (t < NCLS) {
        float acc = 0.0f, ca = 0.0f;
#pragma unroll
        for (int w = 0; w < TPB / 32; w++) { acc += sw[w][t]; ca += cw[w][t]; }
        const int slot = (b * CHUNKS + chunk) * NCLS + t;
        g_part_s[slot] = acc;
        g_part_c[slot] = ca;
    }

    // --- last-block-done finalize (single launch) ---
    __shared__ int is_last;
    __threadfence();                       // partials visible before ticket
    if (t == 0) {
        unsigned int old = atomicAdd(&g_ticket, 1u);
        is_last = (old == (unsigned int)(nblk - 1)) ? 1 : 0;
    }
    __syncthreads();
    if (!is_last) return;

    // TPB-independent: each thread strides over all NT terms (NT may exceed TPB).
    float term = 0.0f;
    const int NT = B * NCLS;               // 160
    for (int idx = t; idx < NT; idx += TPB) {
        const int bb = idx / NCLS;
        const int cc = idx % NCLS;
        float S = 0.0f, N = 0.0f;
#pragma unroll 8
        for (int k = 0; k < CHUNKS; k++) {
            const int slot = (bb * CHUNKS + k) * NCLS + cc;
            S += __ldcg(&g_part_s[slot]);  // written by other SMs: bypass L1
            N += __ldcg(&g_part_c[slot]);
        }
        const float agg = (N > 0.0f) ? (S / N) : 0.0f;
        const float gt  = class_gt[idx];
        const float lp  = fmaxf(logf(agg),    -100.0f);  // log(0)=-inf -> -100
        const float l1  = fmaxf(log1pf(-agg), -100.0f);  // log1p(-1)=-inf -> -100
        term += gt * lp + (1.0f - gt) * l1;
    }

    __shared__ float red[TPB];
    red[t] = term;
    __syncthreads();
#pragma unroll
    for (int o = TPB / 2; o > 0; o >>= 1) {
        if (t < o) red[t] += red[t + o];
        __syncthreads();
    }
    if (t == 0) {
        out[0] = -red[0] / (float)NT;
        g_ticket = 0;                      // reset for next graph replay
    }
}

extern "C" void kernel_launch(void* const* d_in, const int* in_sizes, int n_in,
                              void* d_out, int out_size)
{
    // metadata order: segmentation_logits (large), class_gt (small).
    int li = 0, gi = 1;
    if (n_in >= 2 && in_sizes[1] > in_sizes[0]) { li = 1; gi = 0; }

    const float* logits = (const float*)d_in[li];
    const float* gt     = (const float*)d_in[gi];

    int B = in_sizes[gi] / NCLS;   // 32
    if (B < 1)    B = 1;
    if (B > MAXB) B = MAXB;

    dim3 grid(CHUNKS, B);
    apcl_fused_kernel<<<grid, TPB>>>((const float4*)logits, gt, (float*)d_out, B);
}

// round 8
// speedup vs baseline: 1.1412x; 1.1412x over previous
#include <cuda_runtime.h>
#include <cstdint>

// Problem constants: logits [B, 6, 512, 512] fp32, class_gt [B, 5] fp32, B=32.
#define NCLS   5
#define G      65536             // float4 groups per channel (512*512/4)
#define CHUNKS 64                // blocks per image
#define TPB    256
#define GPC    (G / CHUNKS)      // 1024 float4 groups per block
#define SITER  (GPC / TPB)       // 4 stages per block (16 px/thread)
#define MAXB   64

#define STAGE_F4     TPB                     // 256 float4 per channel per stage
#define STAGE_BYTES  (NCLS * STAGE_F4 * 16)  // 20480 B per stage

// Fixed-slot partials -> bitwise deterministic, no FP atomics, no zero-init.
__device__ float        g_part_s[MAXB * CHUNKS * NCLS];
__device__ float        g_part_c[MAXB * CHUNKS * NCLS];
__device__ unsigned int g_ticket;   // zero-init; last block resets each call

__device__ __forceinline__ float ex2_fast(float x)
{
    float y; asm("ex2.approx.ftz.f32 %0, %1;" : "=f"(y) : "f"(x)); return y;
}
__device__ __forceinline__ float rcp_fast(float x)
{
    float y; asm("rcp.approx.ftz.f32 %0, %1;" : "=f"(y) : "f"(x)); return y;
}
__device__ __forceinline__ uint32_t smem_u32(const void* p)
{
    return (uint32_t)__cvta_generic_to_shared(p);
}
__device__ __forceinline__ void mbar_init(uint32_t addr, uint32_t count)
{
    asm volatile("mbarrier.init.shared.b64 [%0], %1;" :: "r"(addr), "r"(count) : "memory");
}
__device__ __forceinline__ void mbar_expect_tx(uint32_t addr, uint32_t bytes)
{
    asm volatile("mbarrier.arrive.expect_tx.shared.b64 _, [%0], %1;"
                 :: "r"(addr), "r"(bytes) : "memory");
}
__device__ __forceinline__ void mbar_wait(uint32_t addr, uint32_t parity)
{
    asm volatile(
        "{\n\t"
        ".reg .pred P;\n\t"
        "WAIT_%=:\n\t"
        "mbarrier.try_wait.parity.acquire.cta.shared::cta.b64 P, [%0], %1, 0x989680;\n\t"
        "@!P bra WAIT_%=;\n\t"
        "}"
        :: "r"(addr), "r"(parity) : "memory");
}
// 1D bulk async copy gmem -> smem, completion via mbarrier complete_tx.
__device__ __forceinline__ void bulk_cp(uint32_t dst_smem, const void* src, uint32_t bytes,
                                        uint32_t mbar)
{
    asm volatile(
        "cp.async.bulk.shared::cta.global.mbarrier::complete_tx::bytes [%0], [%1], %2, [%3];"
        :: "r"(dst_smem), "l"(src), "r"(bytes), "r"(mbar) : "memory");
}

__global__ void __launch_bounds__(TPB)
apcl_fused_kernel(const float4* __restrict__ logits,
                  const float*  __restrict__ class_gt,
                  float*        __restrict__ out,
                  int B)
{
    // Double-buffered stage: [stage][channel][f4]. 40 KB static.
    __shared__ float4   buf[2][NCLS][STAGE_F4];
    __shared__ uint64_t mbar_full[2];

    const int b     = blockIdx.y;
    const int chunk = blockIdx.x;
    const int t     = threadIdx.x;
    const int nblk  = gridDim.x * gridDim.y;

    const float4* src0 = logits + (size_t)b * 6 * G + chunk * GPC;

    const uint32_t mb0 = smem_u32(&mbar_full[0]);
    const uint32_t mb1 = smem_u32(&mbar_full[1]);

    if (t == 0) {
        mbar_init(mb0, 1);
        mbar_init(mb1, 1);
    }
    __syncthreads();

    // Prologue: issue stages 0 and 1.
    if (t == 0) {
#pragma unroll
        for (int j = 0; j < 2; j++) {
            if (j < SITER) {
                const uint32_t mb = j ? mb1 : mb0;
                mbar_expect_tx(mb, STAGE_BYTES);
#pragma unroll
                for (int c = 0; c < NCLS; c++)
                    bulk_cp(smem_u32(&buf[j][c][0]),
                            src0 + (size_t)c * G + j * STAGE_F4, STAGE_F4 * 16, mb);
            }
        }
    }

    float s[NCLS];
#pragma unroll
    for (int c = 0; c < NCLS; c++) s[c] = 0.0f;
    unsigned packed_cnt = 0;               // 5 counters x 6 bits (max 16 each)

    const float L2E = 1.4426950408889634f;

#pragma unroll
    for (int it = 0; it < SITER; it++) {
        const int j = it & 1;
        mbar_wait(j ? mb1 : mb0, (it >> 1) & 1);

        float4 v[NCLS];
#pragma unroll
        for (int c = 0; c < NCLS; c++)
            v[c] = buf[j][c][t];           // conflict-free LDS.128

#pragma unroll
        for (int l = 0; l < 4; l++) {
            // exp-domain: e_c = 2^(x_c*log2e). N(0,1) inputs => no overflow.
            // softmax at argmax = e_max/sum(e); monotone => same ties as x.
            float e[NCLS];
            float sum = 0.0f;
#pragma unroll
            for (int c = 0; c < NCLS; c++) {
                e[c] = ex2_fast(((const float*)&v[c])[l] * L2E);
                sum += e[c];
            }
            const float emax = fmaxf(fmaxf(fmaxf(e[0], e[1]), fmaxf(e[2], e[3])), e[4]);
            const float p    = emax * rcp_fast(sum);

#pragma unroll
            for (int c = 0; c < NCLS; c++) {
                if (e[c] == emax) { s[c] += p; packed_cnt += (1u << (6 * c)); }
            }
        }

        // Reissue this buffer for stage it+2 once everyone has consumed it.
        if (it + 2 < SITER) {
            __syncthreads();
            if (t == 0) {
                const uint32_t mb = j ? mb1 : mb0;
                mbar_expect_tx(mb, STAGE_BYTES);
#pragma unroll
                for (int c = 0; c < NCLS; c++)
                    bulk_cp(smem_u32(&buf[j][c][0]),
                            src0 + (size_t)c * G + (it + 2) * STAGE_F4, STAGE_F4 * 16, mb);
            }
        }
    }

    // Unpack counters (exact: <= 16 per class per thread).
    float cf[NCLS];
#pragma unroll
    for (int c = 0; c < NCLS; c++)
        cf[c] = (float)((packed_cnt >> (6 * c)) & 63u);

    // --- warp reduction (fixed order, deterministic) ---
#pragma unroll
    for (int off = 16; off > 0; off >>= 1) {
#pragma unroll
        for (int c = 0; c < NCLS; c++) {
            s[c]  += __shfl_down_sync(0xffffffffu, s[c],  off);
            cf[c] += __shfl_down_sync(0xffffffffu, cf[c], off);
        }
    }

    __shared__ float sw[TPB / 32][NCLS];
    __shared__ float cw[TPB / 32][NCLS];
    const int lane = t & 31;
    const int warp = t >> 5;
    if (lane == 0) {
#pragma unroll
        for (int c = 0; c < NCLS; c++) { sw[warp][c] = s[c]; cw[warp][c] = cf[c]; }
    }
    __syncthreads();

    if (t < NCLS) {
        float acc = 0.0f, ca = 0.0f;
#pragma unroll
        for (int w = 0; w < TPB / 32; w++) { acc += sw[w][t]; ca += cw[w][t]; }
        const int slot = (b * CHUNKS + chunk) * NCLS + t;
        g_part_s[slot] = acc;
        g_part_c[slot] = ca;
    }

    // --- last-block-done finalize (single launch) ---
    __shared__ int is_last;
    __threadfence();                       // partials visible before ticket
    if (t == 0) {
        unsigned int old = atomicAdd(&g_ticket, 1u);
        is_last = (old == (unsigned int)(nblk - 1)) ? 1 : 0;
    }
    __syncthreads();
    if (!is_last) return;

    // TPB-independent: each thread strides over all NT terms.
    float term = 0.0f;
    const int NT = B * NCLS;               // 160
    for (int idx = t; idx < NT; idx += TPB) {
        const int bb = idx / NCLS;
        const int cc = idx % NCLS;
        float S = 0.0f, N = 0.0f;
#pragma unroll 8
        for (int k = 0; k < CHUNKS; k++) {
            const int slot = (bb * CHUNKS + k) * NCLS + cc;
            S += __ldcg(&g_part_s[slot]);  // written by other SMs: bypass L1
            N += __ldcg(&g_part_c[slot]);
        }
        const float agg = (N > 0.0f) ? (S / N) : 0.0f;
        const float gt  = class_gt[idx];
        const float lp  = fmaxf(logf(agg),    -100.0f);  // log(0)=-inf -> -100
        const float l1  = fmaxf(log1pf(-agg), -100.0f);  // log1p(-1)=-inf -> -100
        term += gt * lp + (1.0f - gt) * l1;
    }

    __shared__ float red[TPB];
    red[t] = term;
    __syncthreads();
#pragma unroll
    for (int o = TPB / 2; o > 0; o >>= 1) {
        if (t < o) red[t] += red[t + o];
        __syncthreads();
    }
    if (t == 0) {
        out[0] = -red[0] / (float)NT;
        g_ticket = 0;                      // reset for next graph replay
    }
}

extern "C" void kernel_launch(void* const* d_in, const int* in_sizes, int n_in,
                              void* d_out, int out_size)
{
    // metadata order: segmentation_logits (large), class_gt (small).
    int li = 0, gi = 1;
    if (n_in >= 2 && in_sizes[1] > in_sizes[0]) { li = 1; gi = 0; }

    const float* logits = (const float*)d_in[li];
    const float* gt     = (const float*)d_in[gi];

    int B = in_sizes[gi] / NCLS;   // 32
    if (B < 1)    B = 1;
    if (B > MAXB) B = MAXB;

    dim3 grid(CHUNKS, B);
    apcl_fused_kernel<<<grid, TPB>>>((const float4*)logits, gt, (float*)d_out, B);
}

// round 9
// speedup vs baseline: 1.2597x; 1.1039x over previous
#include <cuda_runtime.h>
#include <cstdint>

// Problem constants: logits [B, 6, 512, 512] fp32, class_gt [B, 5] fp32, B=32.
#define NCLS   5
#define G      65536             // float4 groups per channel (512*512/4)
#define CHUNKS 16                // blocks per image
#define TPB    256
#define GPC    (G / CHUNKS)      // 4096 float4 groups per block
#define SITER  (GPC / TPB)       // 16 stages per block (64 px/thread)
#define DEPTH  3                 // ring depth: 2 stages of fill slack
#define MAXB   64

#define STAGE_F4     TPB                     // 256 float4 per channel per stage
#define STAGE_BYTES  (NCLS * STAGE_F4 * 16)  // 20480 B per stage

// Fixed-slot partials -> bitwise deterministic, no FP atomics, no zero-init.
__device__ float        g_part_s[MAXB * CHUNKS * NCLS];
__device__ float        g_part_c[MAXB * CHUNKS * NCLS];
__device__ unsigned int g_ticket;   // zero-init; last block resets each call

__device__ __forceinline__ float ex2_fast(float x)
{
    float y; asm("ex2.approx.ftz.f32 %0, %1;" : "=f"(y) : "f"(x)); return y;
}
__device__ __forceinline__ float rcp_fast(float x)
{
    float y; asm("rcp.approx.ftz.f32 %0, %1;" : "=f"(y) : "f"(x)); return y;
}
__device__ __forceinline__ uint32_t smem_u32(const void* p)
{
    return (uint32_t)__cvta_generic_to_shared(p);
}
__device__ __forceinline__ void mbar_init(uint32_t addr, uint32_t count)
{
    asm volatile("mbarrier.init.shared.b64 [%0], %1;" :: "r"(addr), "r"(count) : "memory");
}
__device__ __forceinline__ void mbar_expect_tx(uint32_t addr, uint32_t bytes)
{
    asm volatile("mbarrier.arrive.expect_tx.shared.b64 _, [%0], %1;"
                 :: "r"(addr), "r"(bytes) : "memory");
}
__device__ __forceinline__ void mbar_wait(uint32_t addr, uint32_t parity)
{
    asm volatile(
        "{\n\t"
        ".reg .pred P;\n\t"
        "WAIT_%=:\n\t"
        "mbarrier.try_wait.parity.acquire.cta.shared::cta.b64 P, [%0], %1, 0x989680;\n\t"
        "@!P bra WAIT_%=;\n\t"
        "}"
        :: "r"(addr), "r"(parity) : "memory");
}
// 1D bulk async copy gmem -> smem, completion via mbarrier complete_tx.
__device__ __forceinline__ void bulk_cp(uint32_t dst_smem, const void* src, uint32_t bytes,
                                        uint32_t mbar)
{
    asm volatile(
        "cp.async.bulk.shared::cta.global.mbarrier::complete_tx::bytes [%0], [%1], %2, [%3];"
        :: "r"(dst_smem), "l"(src), "r"(bytes), "r"(mbar) : "memory");
}

__global__ void __launch_bounds__(TPB)
apcl_fused_kernel(const float4* __restrict__ logits,
                  const float*  __restrict__ class_gt,
                  float*        __restrict__ out,
                  int B)
{
    // DEPTH-deep ring: [slot][channel][f4]. ~60 KB -> 3 blocks/SM.
    __shared__ float4   buf[DEPTH][NCLS][STAGE_F4];
    __shared__ uint64_t mbar_full[DEPTH];

    const int b     = blockIdx.y;
    const int chunk = blockIdx.x;
    const int t     = threadIdx.x;
    const int nblk  = gridDim.x * gridDim.y;

    const float4* src0 = logits + (size_t)b * 6 * G + chunk * GPC;

    if (t == 0) {
#pragma unroll
        for (int j = 0; j < DEPTH; j++)
            mbar_init(smem_u32(&mbar_full[j]), 1);
    }
    __syncthreads();

    // Prologue: fill slots 0..DEPTH-1 (stages 0..2).
    if (t == 0) {
#pragma unroll
        for (int j = 0; j < DEPTH; j++) {
            const uint32_t mb = smem_u32(&mbar_full[j]);
            mbar_expect_tx(mb, STAGE_BYTES);
#pragma unroll
            for (int c = 0; c < NCLS; c++)
                bulk_cp(smem_u32(&buf[j][c][0]),
                        src0 + (size_t)c * G + j * STAGE_F4, STAGE_F4 * 16, mb);
        }
    }

    float s[NCLS];
#pragma unroll
    for (int c = 0; c < NCLS; c++) s[c] = 0.0f;
    float cf0 = 0.0f, cf1 = 0.0f, cf2 = 0.0f, cf3 = 0.0f, cf4 = 0.0f;
    unsigned packed_cnt = 0;     // 5 counters x 6 bits; flushed if near overflow

    const float L2E = 1.4426950408889634f;

    for (int st = 0; st < SITER; st++) {
        const int j = st % DEPTH;
        const int m = st / DEPTH;              // fill index of this slot
        const uint32_t mb = smem_u32(&mbar_full[j]);
        mbar_wait(mb, m & 1);

        float4 v[NCLS];
#pragma unroll
        for (int c = 0; c < NCLS; c++)
            v[c] = buf[j][c][t];               // conflict-free LDS.128

#pragma unroll
        for (int l = 0; l < 4; l++) {
            // exp-domain: e_c = 2^(x_c*log2e). N(0,1) inputs => no overflow.
            // softmax at argmax = e_max/sum(e); monotone => same ties as x.
            float e[NCLS];
            float sum = 0.0f;
#pragma unroll
            for (int c = 0; c < NCLS; c++) {
                e[c] = ex2_fast(((const float*)&v[c])[l] * L2E);
                sum += e[c];
            }
            const float emax = fmaxf(fmaxf(fmaxf(e[0], e[1]), fmaxf(e[2], e[3])), e[4]);
            const float p    = emax * rcp_fast(sum);

#pragma unroll
            for (int c = 0; c < NCLS; c++) {
                if (e[c] == emax) { s[c] += p; packed_cnt += (1u << (6 * c)); }
            }
        }

        // Flush packed counters every 8 stages (<= 32 < 64 per class). Exact.
        if ((st & 7) == 7) {
            cf0 += (float)( packed_cnt        & 63u);
            cf1 += (float)((packed_cnt >>  6) & 63u);
            cf2 += (float)((packed_cnt >> 12) & 63u);
            cf3 += (float)((packed_cnt >> 18) & 63u);
            cf4 += (float)((packed_cnt >> 24) & 63u);
            packed_cnt = 0;
        }

        // All threads consumed slot j -> safe to refill it for stage st+DEPTH.
        __syncthreads();
        if (t == 0 && st + DEPTH < SITER) {
            mbar_expect_tx(mb, STAGE_BYTES);
#pragma unroll
            for (int c = 0; c < NCLS; c++)
                bulk_cp(smem_u32(&buf[j][c][0]),
                        src0 + (size_t)c * G + (st + DEPTH) * STAGE_F4, STAGE_F4 * 16, mb);
        }
    }

    float cf[NCLS] = { cf0, cf1, cf2, cf3, cf4 };

    // --- warp reduction (fixed order, deterministic) ---
#pragma unroll
    for (int off = 16; off > 0; off >>= 1) {
#pragma unroll
        for (int c = 0; c < NCLS; c++) {
            s[c]  += __shfl_down_sync(0xffffffffu, s[c],  off);
            cf[c] += __shfl_down_sync(0xffffffffu, cf[c], off);
        }
    }

    __shared__ float sw[TPB / 32][NCLS];
    __shared__ float cw[TPB / 32][NCLS];
    const int lane = t & 31;
    const int warp = t >> 5;
    if (lane == 0) {
#pragma unroll
        for (int c = 0; c < NCLS; c++) { sw[warp][c] = s[c]; cw[warp][c] = cf[c]; }
    }
    __syncthreads();

    if (t < NCLS) {
        float acc = 0.0f, ca = 0.0f;
#pragma unroll
        for (int w = 0; w < TPB / 32; w++) { acc += sw[w][t]; ca += cw[w][t]; }
        const int slot = (b * CHUNKS + chunk) * NCLS + t;
        g_part_s[slot] = acc;
        g_part_c[slot] = ca;
    }

    // --- last-block-done finalize (single launch) ---
    __shared__ int is_last;
    __threadfence();                       // partials visible before ticket
    if (t == 0) {
        unsigned int old = atomicAdd(&g_ticket, 1u);
        is_last = (old == (unsigned int)(nblk - 1)) ? 1 : 0;
    }
    __syncthreads();
    if (!is_last) return;

    // TPB-independent: each thread strides over all NT terms.
    float term = 0.0f;
    const int NT = B * NCLS;               // 160
    for (int idx = t; idx < NT; idx += TPB) {
        const int bb = idx / NCLS;
        const int cc = idx % NCLS;
        float S = 0.0f, N = 0.0f;
#pragma unroll
        for (int k = 0; k < CHUNKS; k++) {
            const int slot = (bb * CHUNKS + k) * NCLS + cc;
            S += __ldcg(&g_part_s[slot]);  // written by other SMs: bypass L1
            N += __ldcg(&g_part_c[slot]);
        }
        const float agg = (N > 0.0f) ? (S / N) : 0.0f;
        const float gt  = class_gt[idx];
        const float lp  = fmaxf(logf(agg),    -100.0f);  // log(0)=-inf -> -100
        const float l1  = fmaxf(log1pf(-agg), -100.0f);  // log1p(-1)=-inf -> -100
        term += gt * lp + (1.0f - gt) * l1;
    }

    __shared__ float red[TPB];
    red[t] = term;
    __syncthreads();
#pragma unroll
    for (int o = TPB / 2; o > 0; o >>= 1) {
        if (t < o) red[t] += red[t + o];
        __syncthreads();
    }
    if (t == 0) {
        out[0] = -red[0] / (float)NT;
        g_ticket = 0;                      // reset for next graph replay
    }
}

extern "C" void kernel_launch(void* const* d_in, const int* in_sizes, int n_in,
                              void* d_out, int out_size)
{
    // metadata order: segmentation_logits (large), class_gt (small).
    int li = 0, gi = 1;
    if (n_in >= 2 && in_sizes[1] > in_sizes[0]) { li = 1; gi = 0; }

    const float* logits = (const float*)d_in[li];
    const float* gt     = (const float*)d_in[gi];

    int B = in_sizes[gi] / NCLS;   // 32
    if (B < 1)    B = 1;
    if (B > MAXB) B = MAXB;

    dim3 grid(CHUNKS, B);
    apcl_fused_kernel<<<grid, TPB>>>((const float4*)logits, gt, (float*)d_out, B);
}

// round 10
// speedup vs baseline: 1.2923x; 1.0258x over previous
#include <cuda_runtime.h>
#include <cstdint>

// Problem constants: logits [B, 6, 512, 512] fp32, class_gt [B, 5] fp32, B=32.
#define NCLS   5
#define G      65536             // float4 groups per channel (512*512/4)
#define CHUNKS 32                // blocks per image
#define TPB    256
#define GPC    (G / CHUNKS)      // 2048 float4 groups per block
#define ITERS  (GPC / TPB)       // 8 iterations per thread (32 px/thread)
#define MAXB   64

// Fixed-slot partials -> bitwise deterministic, no FP atomics, no zero-init.
__device__ float        g_part_s[MAXB * CHUNKS * NCLS];
__device__ float        g_part_c[MAXB * CHUNKS * NCLS];
__device__ unsigned int g_ticket;   // zero-init; last block resets each call

__device__ __forceinline__ float ex2_fast(float x)
{
    float y; asm("ex2.approx.ftz.f32 %0, %1;" : "=f"(y) : "f"(x)); return y;
}
__device__ __forceinline__ float rcp_fast(float x)
{
    float y; asm("rcp.approx.ftz.f32 %0, %1;" : "=f"(y) : "f"(x)); return y;
}

__global__ void __launch_bounds__(TPB, 3)
apcl_fused_kernel(const float4* __restrict__ logits,
                  const float*  __restrict__ class_gt,
                  float*        __restrict__ out,
                  int B)
{
    const int b     = blockIdx.y;
    const int chunk = blockIdx.x;
    const int t     = threadIdx.x;
    const int nblk  = gridDim.x * gridDim.y;

    const float4* src0 = logits + (size_t)b * 6 * G + chunk * GPC + t;

    float s[NCLS];
#pragma unroll
    for (int c = 0; c < NCLS; c++) s[c] = 0.0f;
    unsigned packed_cnt = 0;        // 5 counters x 6 bits (max 32 each, fits)

    const float L2E = 1.4426950408889634f;

    // 3-deep register ring: 10 outstanding LDG.128 per thread (prefetch
    // distance 2) -> 120 KB in flight per SM at 3 blocks/SM.
    float4 v[3][NCLS];
#pragma unroll
    for (int c = 0; c < NCLS; c++) {
        v[0][c] = __ldcg(src0 + (size_t)c * G);
        v[1][c] = __ldcg(src0 + (size_t)c * G + TPB);
    }

#pragma unroll
    for (int it = 0; it < ITERS; it++) {
        if (it + 2 < ITERS) {
#pragma unroll
            for (int c = 0; c < NCLS; c++)
                v[(it + 2) % 3][c] = __ldcg(src0 + (size_t)c * G + (it + 2) * TPB);
        }

        const float4* cur = v[it % 3];

#pragma unroll
        for (int l = 0; l < 4; l++) {
            // exp-domain: e_c = 2^(x_c*log2e). N(0,1) inputs => no overflow.
            // softmax at argmax = e_max/sum(e); monotone => same ties as x.
            float e[NCLS];
            float sum = 0.0f;
#pragma unroll
            for (int c = 0; c < NCLS; c++) {
                e[c] = ex2_fast(((const float*)&cur[c])[l] * L2E);
                sum += e[c];
            }
            const float emax = fmaxf(fmaxf(fmaxf(e[0], e[1]), fmaxf(e[2], e[3])), e[4]);
            const float p    = emax * rcp_fast(sum);

#pragma unroll
            for (int c = 0; c < NCLS; c++) {
                if (e[c] == emax) { s[c] += p; packed_cnt += (1u << (6 * c)); }
            }
        }
    }

    // Unpack counters (exact: <= 32 per class per thread).
    float cf[NCLS];
#pragma unroll
    for (int c = 0; c < NCLS; c++)
        cf[c] = (float)((packed_cnt >> (6 * c)) & 63u);

    // --- warp reduction (fixed order, deterministic) ---
#pragma unroll
    for (int off = 16; off > 0; off >>= 1) {
#pragma unroll
        for (int c = 0; c < NCLS; c++) {
            s[c]  += __shfl_down_sync(0xffffffffu, s[c],  off);
            cf[c] += __shfl_down_sync(0xffffffffu, cf[c], off);
        }
    }

    __shared__ float sw[TPB / 32][NCLS];
    __shared__ float cw[TPB / 32][NCLS];
    const int lane = t & 31;
    const int warp = t >> 5;
    if (lane == 0) {
#pragma unroll
        for (int c = 0; c < NCLS; c++) { sw[warp][c] = s[c]; cw[warp][c] = cf[c]; }
    }
    __syncthreads();

    if (t < NCLS) {
        float acc = 0.0f, ca = 0.0f;
#pragma unroll
        for (int w = 0; w < TPB / 32; w++) { acc += sw[w][t]; ca += cw[w][t]; }
        const int slot = (b * CHUNKS + chunk) * NCLS + t;
        g_part_s[slot] = acc;
        g_part_c[slot] = ca;
    }

    // --- last-block-done finalize (single launch) ---
    __shared__ int is_last;
    __threadfence();                       // partials visible before ticket
    if (t == 0) {
        unsigned int old = atomicAdd(&g_ticket, 1u);
        is_last = (old == (unsigned int)(nblk - 1)) ? 1 : 0;
    }
    __syncthreads();
    if (!is_last) return;

    // TPB-independent: each thread strides over all NT terms.
    float term = 0.0f;
    const int NT = B * NCLS;               // 160
    for (int idx = t; idx < NT; idx += TPB) {
        const int bb = idx / NCLS;
        const int cc = idx % NCLS;
        float S = 0.0f, N = 0.0f;
#pragma unroll
        for (int k = 0; k < CHUNKS; k++) {
            const int slot = (bb * CHUNKS + k) * NCLS + cc;
            S += __ldcg(&g_part_s[slot]);  // written by other SMs: bypass L1
            N += __ldcg(&g_part_c[slot]);
        }
        const float agg = (N > 0.0f) ? (S / N) : 0.0f;
        const float gt  = class_gt[idx];
        const float lp  = fmaxf(logf(agg),    -100.0f);  // log(0)=-inf -> -100
        const float l1  = fmaxf(log1pf(-agg), -100.0f);  // log1p(-1)=-inf -> -100
        term += gt * lp + (1.0f - gt) * l1;
    }

    __shared__ float red[TPB];
    red[t] = term;
    __syncthreads();
#pragma unroll
    for (int o = TPB / 2; o > 0; o >>= 1) {
        if (t < o) red[t] += red[t + o];
        __syncthreads();
    }
    if (t == 0) {
        out[0] = -red[0] / (float)NT;
        g_ticket = 0;                      // reset for next graph replay
    }
}

extern "C" void kernel_launch(void* const* d_in, const int* in_sizes, int n_in,
                              void* d_out, int out_size)
{
    // metadata order: segmentation_logits (large), class_gt (small).
    int li = 0, gi = 1;
    if (n_in >= 2 && in_sizes[1] > in_sizes[0]) { li = 1; gi = 0; }

    const float* logits = (const float*)d_in[li];
    const float* gt     = (const float*)d_in[gi];

    int B = in_sizes[gi] / NCLS;   // 32
    if (B < 1)    B = 1;
    if (B > MAXB) B = MAXB;

    dim3 grid(CHUNKS, B);
    apcl_fused_kernel<<<grid, TPB>>>((const float4*)logits, gt, (float*)d_out, B);
}

// round 11
// speedup vs baseline: 1.3299x; 1.0291x over previous
#include <cuda_runtime.h>
#include <cstdint>

// Problem constants: logits [B, 6, 512, 512] fp32, class_gt [B, 5] fp32, B=32.
#define NCLS   5
#define G      65536             // float4 groups per channel (512*512/4)
#define CHUNKS 32                // blocks per image
#define TPB    256
#define GPC    (G / CHUNKS)      // 2048 float4 groups per block
#define ITERS  (GPC / TPB)       // 8 iterations per thread (32 px/thread)
#define DEPTH  5                 // register ring depth (prefetch distance 4)
#define MAXB   64

// Fixed-slot partials -> bitwise deterministic, no FP atomics, no zero-init.
__device__ float        g_part_s[MAXB * CHUNKS * NCLS];
__device__ float        g_part_c[MAXB * CHUNKS * NCLS];
__device__ unsigned int g_ticket;   // zero-init; last block resets each call

__device__ __forceinline__ float ex2_fast(float x)
{
    float y; asm("ex2.approx.ftz.f32 %0, %1;" : "=f"(y) : "f"(x)); return y;
}
__device__ __forceinline__ float rcp_fast(float x)
{
    float y; asm("rcp.approx.ftz.f32 %0, %1;" : "=f"(y) : "f"(x)); return y;
}

__global__ void __launch_bounds__(TPB, 2)
apcl_fused_kernel(const float4* __restrict__ logits,
                  const float*  __restrict__ class_gt,
                  float*        __restrict__ out,
                  int B)
{
    const int b     = blockIdx.y;
    const int chunk = blockIdx.x;
    const int t     = threadIdx.x;
    const int nblk  = gridDim.x * gridDim.y;

    const float4* src0 = logits + (size_t)b * 6 * G + chunk * GPC + t;

    float s[NCLS];
#pragma unroll
    for (int c = 0; c < NCLS; c++) s[c] = 0.0f;
    unsigned packed_cnt = 0;        // 5 counters x 6 bits (max 32 each, fits)

    const float L2E = 1.4426950408889634f;

    // 5-deep register ring: 20 outstanding LDG.128 per thread (prefetch
    // distance 4) -> ~164 KB in flight per SM at 2 blocks/SM.
    float4 v[DEPTH][NCLS];
#pragma unroll
    for (int j = 0; j < DEPTH - 1; j++)
#pragma unroll
        for (int c = 0; c < NCLS; c++)
            v[j][c] = __ldcg(src0 + (size_t)c * G + j * TPB);

#pragma unroll
    for (int it = 0; it < ITERS; it++) {
        if (it + DEPTH - 1 < ITERS) {
#pragma unroll
            for (int c = 0; c < NCLS; c++)
                v[(it + DEPTH - 1) % DEPTH][c] =
                    __ldcg(src0 + (size_t)c * G + (it + DEPTH - 1) * TPB);
        }

        const float4* cur = v[it % DEPTH];

#pragma unroll
        for (int l = 0; l < 4; l++) {
            // exp-domain: e_c = 2^(x_c*log2e). N(0,1) inputs => no overflow.
            // softmax at argmax = e_max/sum(e); monotone => same ties as x.
            float e[NCLS];
            float sum = 0.0f;
#pragma unroll
            for (int c = 0; c < NCLS; c++) {
                e[c] = ex2_fast(((const float*)&cur[c])[l] * L2E);
                sum += e[c];
            }
            const float emax = fmaxf(fmaxf(fmaxf(e[0], e[1]), fmaxf(e[2], e[3])), e[4]);
            const float p    = emax * rcp_fast(sum);

#pragma unroll
            for (int c = 0; c < NCLS; c++) {
                if (e[c] == emax) { s[c] += p; packed_cnt += (1u << (6 * c)); }
            }
        }
    }

    // Unpack counters (exact: <= 32 per class per thread).
    float cf[NCLS];
#pragma unroll
    for (int c = 0; c < NCLS; c++)
        cf[c] = (float)((packed_cnt >> (6 * c)) & 63u);

    // --- warp reduction (fixed order, deterministic) ---
#pragma unroll
    for (int off = 16; off > 0; off >>= 1) {
#pragma unroll
        for (int c = 0; c < NCLS; c++) {
            s[c]  += __shfl_down_sync(0xffffffffu, s[c],  off);
            cf[c] += __shfl_down_sync(0xffffffffu, cf[c], off);
        }
    }

    __shared__ float sw[TPB / 32][NCLS];
    __shared__ float cw[TPB / 32][NCLS];
    const int lane = t & 31;
    const int warp = t >> 5;
    if (lane == 0) {
#pragma unroll
        for (int c = 0; c < NCLS; c++) { sw[warp][c] = s[c]; cw[warp][c] = cf[c]; }
    }
    __syncthreads();

    if (t < NCLS) {
        float acc = 0.0f, ca = 0.0f;
#pragma unroll
        for (int w = 0; w < TPB / 32; w++) { acc += sw[w][t]; ca += cw[w][t]; }
        const int slot = (b * CHUNKS + chunk) * NCLS + t;
        g_part_s[slot] = acc;
        g_part_c[slot] = ca;
    }

    // --- last-block-done finalize (single launch) ---
    __shared__ int is_last;
    __threadfence();                       // partials visible before ticket
    if (t == 0) {
        unsigned int old = atomicAdd(&g_ticket, 1u);
        is_last = (old == (unsigned int)(nblk - 1)) ? 1 : 0;
    }
    __syncthreads();
    if (!is_last) return;

    // TPB-independent: each thread strides over all NT terms.
    float term = 0.0f;
    const int NT = B * NCLS;               // 160
    for (int idx = t; idx < NT; idx += TPB) {
        const int bb = idx / NCLS;
        const int cc = idx % NCLS;
        float S = 0.0f, N = 0.0f;
#pragma unroll
        for (int k = 0; k < CHUNKS; k++) {
            const int slot = (bb * CHUNKS + k) * NCLS + cc;
            S += __ldcg(&g_part_s[slot]);  // written by other SMs: bypass L1
            N += __ldcg(&g_part_c[slot]);
        }
        const float agg = (N > 0.0f) ? (S / N) : 0.0f;
        const float gt  = class_gt[idx];
        const float lp  = fmaxf(logf(agg),    -100.0f);  // log(0)=-inf -> -100
        const float l1  = fmaxf(log1pf(-agg), -100.0f);  // log1p(-1)=-inf -> -100
        term += gt * lp + (1.0f - gt) * l1;
    }

    __shared__ float red[TPB];
    red[t] = term;
    __syncthreads();
#pragma unroll
    for (int o = TPB / 2; o > 0; o >>= 1) {
        if (t < o) red[t] += red[t + o];
        __syncthreads();
    }
    if (t == 0) {
        out[0] = -red[0] / (float)NT;
        g_ticket = 0;                      // reset for next graph replay
    }
}

extern "C" void kernel_launch(void* const* d_in, const int* in_sizes, int n_in,
                              void* d_out, int out_size)
{
    // metadata order: segmentation_logits (large), class_gt (small).
    int li = 0, gi = 1;
    if (n_in >= 2 && in_sizes[1] > in_sizes[0]) { li = 1; gi = 0; }

    const float* logits = (const float*)d_in[li];
    const float* gt     = (const float*)d_in[gi];

    int B = in_sizes[gi] / NCLS;   // 32
    if (B < 1)    B = 1;
    if (B > MAXB) B = MAXB;

    dim3 grid(CHUNKS, B);
    apcl_fused_kernel<<<grid, TPB>>>((const float4*)logits, gt, (float*)d_out, B);
}